// round 2
// baseline (speedup 1.0000x reference)
#include <cuda_runtime.h>
#include <math.h>

#define NB 8
#define NS 256
#define NH 768
#define NL 20
#define NLS 8
#define NE 300
#define NEGV -10000.0f
#define NBS (NB*NS)        /* 2048 */
#define MFIN (NBS*NL)      /* 40960 */
#define KFIN 1536

// ---------------- scratch (static device memory; no allocation) ----------------
__device__ float g_tkn[NBS*NH];          // tkn = token @ W1^T            [2048,768]
__device__ float g_T1 [NBS*NH];          // tkn @ W5a^T                   [2048,768]
__device__ float g_lab[NL*NLS*NH];       // label_embs @ W2^T             [160,768]
__device__ float g_lw5b[NL*NLS*NH];      // lab @ W5b^T                   [160,768]
__device__ float g_a  [MFIN*NLS];        // softmax over t, [(l*2048+bs)*8+t]
__device__ float g_bin[NB*NL*NS];        // [(b*20+l)*256+s]
__device__ float g_q2c[NB*NL*NH];        // [160,768]
__device__ float g_XY [(size_t)MFIN*KFIN]; // [l*2048+bs][0:768]=tkn*c2q, [768:1536]=tkn*q2c

// ---------------- f32x2 helpers ----------------
__device__ __forceinline__ unsigned long long pk2(float x){
    unsigned long long r; asm("mov.b64 %0, {%1, %1};" : "=l"(r) : "f"(x)); return r;
}
__device__ __forceinline__ unsigned long long fma2(unsigned long long a,
                                                   unsigned long long b,
                                                   unsigned long long c){
    unsigned long long d;
    asm("fma.rn.f32x2 %0, %1, %2, %3;" : "=l"(d) : "l"(a), "l"(b), "l"(c));
    return d;
}
__device__ __forceinline__ float2 up2(unsigned long long v){
    float2 f; asm("mov.b64 {%0, %1}, %2;" : "=f"(f.x), "=f"(f.y) : "l"(v)); return f;
}

// ---------------- lab = label_embs @ W2^T ----------------
__global__ void klab(const float* __restrict__ lemb, const float* __restrict__ W2){
    __shared__ float er[NE];
    int lt = blockIdx.x;
    for (int i = threadIdx.x; i < NE; i += blockDim.x) er[i] = lemb[lt*NE + i];
    __syncthreads();
    for (int o = threadIdx.x; o < NH; o += blockDim.x){
        const float* w = W2 + (size_t)o*NE;
        float s = 0.f;
        #pragma unroll 4
        for (int e = 0; e < NE; e++) s += er[e]*w[e];
        g_lab[lt*NH + o] = s;
    }
}

// ---------------- labW5b = lab @ W5b^T ----------------
__global__ void klw5b(const float* __restrict__ W5){
    __shared__ float lr[NH];
    int lt = blockIdx.x;
    for (int i = threadIdx.x; i < NH; i += blockDim.x) lr[i] = g_lab[lt*NH + i];
    __syncthreads();
    for (int o = threadIdx.x; o < NH; o += blockDim.x){
        const float4* w = (const float4*)(W5 + (size_t)o*3072 + NH);
        const float4* a = (const float4*)lr;
        float s = 0.f;
        #pragma unroll 4
        for (int i = 0; i < NH/4; i++){
            float4 x = a[i], y = w[i];
            s += x.x*y.x + x.y*y.y + x.z*y.z + x.w*y.w;
        }
        g_lw5b[lt*NH + o] = s;
    }
}

// ---------------- generic 128x128 fp32x2 GEMM: C[m,n] = sum_k A[m,k]*B[n,k] ----------------
__global__ __launch_bounds__(256,2) void gemm_plain(
    const float* __restrict__ A, int lda,
    const float* __restrict__ B, int ldb,
    float* __restrict__ C, int ldc, int Kdim)
{
    __shared__ float As[2][8][128];
    __shared__ float Bs[2][8][128];
    const int tid = threadIdx.x;
    const int m0 = blockIdx.y*128, n0 = blockIdx.x*128;
    const int lrow = tid>>1, lcol = (tid&1)*4;
    const float* Ag = A + (size_t)(m0+lrow)*lda + lcol;
    const float* Bg = B + (size_t)(n0+lrow)*ldb + lcol;
    const int tx = tid&15, ty = tid>>4;

    unsigned long long acc[8][4];
    #pragma unroll
    for (int i=0;i<8;i++)
        #pragma unroll
        for (int j=0;j<4;j++) acc[i][j]=0ull;

    const int nk = Kdim>>3;
    float4 ra = *(const float4*)Ag;
    float4 rb = *(const float4*)Bg;
    #pragma unroll
    for (int j=0;j<4;j++){
        As[0][lcol+j][lrow] = ((const float*)&ra)[j];
        Bs[0][lcol+j][lrow] = ((const float*)&rb)[j];
    }
    __syncthreads();
    int buf = 0;
    for (int kt=0; kt<nk; kt++){
        float4 na, nb;
        if (kt+1 < nk){
            na = *(const float4*)(Ag + (size_t)(kt+1)*8);
            nb = *(const float4*)(Bg + (size_t)(kt+1)*8);
        }
        #pragma unroll
        for (int k=0;k<8;k++){
            float av[8];
            *(float4*)&av[0] = *(const float4*)&As[buf][k][ty*8];
            *(float4*)&av[4] = *(const float4*)&As[buf][k][ty*8+4];
            unsigned long long b2[4];
            #pragma unroll
            for (int j=0;j<4;j++)
                b2[j] = *(const unsigned long long*)&Bs[buf][k][tx*8+2*j];
            #pragma unroll
            for (int i=0;i<8;i++){
                unsigned long long a2 = pk2(av[i]);
                #pragma unroll
                for (int j=0;j<4;j++) acc[i][j] = fma2(a2, b2[j], acc[i][j]);
            }
        }
        if (kt+1 < nk){
            buf ^= 1;
            #pragma unroll
            for (int j=0;j<4;j++){
                As[buf][lcol+j][lrow] = ((const float*)&na)[j];
                Bs[buf][lcol+j][lrow] = ((const float*)&nb)[j];
            }
        }
        __syncthreads();
    }
    #pragma unroll
    for (int i=0;i<8;i++){
        int m = m0 + ty*8 + i;
        float o[8];
        #pragma unroll
        for (int j=0;j<4;j++){ float2 p = up2(acc[i][j]); o[2*j]=p.x; o[2*j+1]=p.y; }
        float* cp = C + (size_t)m*ldc + n0 + tx*8;
        *(float4*)cp     = make_float4(o[0],o[1],o[2],o[3]);
        *(float4*)(cp+4) = make_float4(o[4],o[5],o[6],o[7]);
    }
}

// ---------------- scores + softmax over t + rowmax ----------------
__global__ void k_scores(const float* __restrict__ lmask, const float* __restrict__ imask){
    __shared__ float tr[NH];
    __shared__ float sc[NL*NLS];
    int bs = blockIdx.x;
    int b = bs >> 8;
    int tid = threadIdx.x;
    for (int i=tid; i<NH; i+=blockDim.x) tr[i] = g_tkn[(size_t)bs*NH + i];
    __syncthreads();
    if (tid < NL*NLS){
        const float4* lr = (const float4*)(g_lab + (size_t)tid*NH);
        const float4* tv = (const float4*)tr;
        float s = 0.f;
        #pragma unroll 4
        for (int i=0;i<NH/4;i++){
            float4 x = lr[i], y = tv[i];
            s += x.x*y.x + x.y*y.y + x.z*y.z + x.w*y.w;
        }
        sc[tid] = s + (1.0f - lmask[tid])*NEGV;
    }
    __syncthreads();
    if (tid < NL){
        int l = tid;
        float mx = -1e30f;
        #pragma unroll
        for (int t=0;t<NLS;t++) mx = fmaxf(mx, sc[l*NLS+t]);
        float ex[NLS]; float sm = 0.f;
        #pragma unroll
        for (int t=0;t<NLS;t++){ ex[t] = expf(sc[l*NLS+t]-mx); sm += ex[t]; }
        float inv = 1.0f/sm;
        int m = l*NBS + bs;
        #pragma unroll
        for (int t=0;t<NLS;t++) g_a[(size_t)m*NLS + t] = ex[t]*inv;
        g_bin[(b*NL + l)*NS + (bs & 255)] = mx + (1.0f - imask[bs])*NEGV;
    }
}

// ---------------- softmax over s + q2c ----------------
__global__ void k_q2c(){
    __shared__ float w[NS];
    __shared__ float red[256];
    int blk = blockIdx.x;         // b*NL + l
    int b = blk / NL;
    int tid = threadIdx.x;
    float v = g_bin[blk*NS + tid];
    red[tid] = v; __syncthreads();
    for (int off=128; off>0; off>>=1){
        if (tid < off) red[tid] = fmaxf(red[tid], red[tid+off]);
        __syncthreads();
    }
    float mx = red[0]; __syncthreads();
    float e = expf(v - mx);
    red[tid] = e; __syncthreads();
    for (int off=128; off>0; off>>=1){
        if (tid < off) red[tid] += red[tid+off];
        __syncthreads();
    }
    float inv = 1.0f/red[0];
    w[tid] = e*inv;
    __syncthreads();
    for (int h=tid; h<NH; h+=blockDim.x){
        float acc = 0.f;
        #pragma unroll 4
        for (int s=0;s<NS;s++) acc += w[s]*g_tkn[(size_t)(b*NS+s)*NH + h];
        g_q2c[(size_t)blk*NH + h] = acc;
    }
}

// ---------------- build XY = [tkn*c2q | tkn*q2c], layout m = l*2048+bs ----------------
__global__ void k_xy(){
    __shared__ float labs[NLS*NH];   // 24 KB
    int l = blockIdx.y;
    int bs0 = blockIdx.x*8;
    int tid = threadIdx.x;
    for (int i=tid; i<NLS*NH; i+=blockDim.x) labs[i] = g_lab[(size_t)l*NLS*NH + i];
    __syncthreads();
    for (int j=0;j<8;j++){
        int bs = bs0 + j;
        int b = bs >> 8;
        int m = l*NBS + bs;
        const float* ap = g_a + (size_t)m*NLS;
        float a0=ap[0],a1=ap[1],a2=ap[2],a3=ap[3],a4=ap[4],a5=ap[5],a6=ap[6],a7=ap[7];
        const float* q = g_q2c + (size_t)(b*NL + l)*NH;
        const float* tk = g_tkn + (size_t)bs*NH;
        float* xy = g_XY + (size_t)m*KFIN;
        for (int k=tid; k<NH; k+=blockDim.x){
            float c2 = a0*labs[k]        + a1*labs[NH+k]   + a2*labs[2*NH+k] + a3*labs[3*NH+k]
                     + a4*labs[4*NH+k]   + a5*labs[5*NH+k] + a6*labs[6*NH+k] + a7*labs[7*NH+k];
            float t = tk[k];
            xy[k]      = t*c2;
            xy[NH + k] = t*q[k];
        }
    }
}

// ---------------- final GEMM + fused epilogue (term1 + term2 + b5 + tanh) ----------------
__global__ __launch_bounds__(256,2) void gemm_final(
    const float* __restrict__ W5, const float* __restrict__ b5,
    float* __restrict__ out)
{
    __shared__ float As[2][8][128];
    __shared__ float Bs[2][8][128];
    const int tid = threadIdx.x;
    const int m0 = blockIdx.y*128, n0 = blockIdx.x*128;
    const int lrow = tid>>1, lcol = (tid&1)*4;
    const float* Ag = g_XY + (size_t)(m0+lrow)*KFIN + lcol;
    const float* Bg = W5 + (size_t)(n0+lrow)*3072 + 1536 + lcol;   // [W5c | W5d]
    const int tx = tid&15, ty = tid>>4;

    unsigned long long acc[8][4];
    #pragma unroll
    for (int i=0;i<8;i++)
        #pragma unroll
        for (int j=0;j<4;j++) acc[i][j]=0ull;

    const int nk = KFIN>>3;   // 192
    float4 ra = *(const float4*)Ag;
    float4 rb = *(const float4*)Bg;
    #pragma unroll
    for (int j=0;j<4;j++){
        As[0][lcol+j][lrow] = ((const float*)&ra)[j];
        Bs[0][lcol+j][lrow] = ((const float*)&rb)[j];
    }
    __syncthreads();
    int buf = 0;
    for (int kt=0; kt<nk; kt++){
        float4 na, nb;
        if (kt+1 < nk){
            na = *(const float4*)(Ag + (size_t)(kt+1)*8);
            nb = *(const float4*)(Bg + (size_t)(kt+1)*8);
        }
        #pragma unroll
        for (int k=0;k<8;k++){
            float av[8];
            *(float4*)&av[0] = *(const float4*)&As[buf][k][ty*8];
            *(float4*)&av[4] = *(const float4*)&As[buf][k][ty*8+4];
            unsigned long long b2[4];
            #pragma unroll
            for (int j=0;j<4;j++)
                b2[j] = *(const unsigned long long*)&Bs[buf][k][tx*8+2*j];
            #pragma unroll
            for (int i=0;i<8;i++){
                unsigned long long a2 = pk2(av[i]);
                #pragma unroll
                for (int j=0;j<4;j++) acc[i][j] = fma2(a2, b2[j], acc[i][j]);
            }
        }
        if (kt+1 < nk){
            buf ^= 1;
            #pragma unroll
            for (int j=0;j<4;j++){
                As[buf][lcol+j][lrow] = ((const float*)&na)[j];
                Bs[buf][lcol+j][lrow] = ((const float*)&nb)[j];
            }
        }
        __syncthreads();
    }

    // epilogue: fixed l per M-tile (2048 % 128 == 0)
    const int l = m0 >> 11;
    const int bsbase = m0 & 2047;
    float* lw  = &As[0][0][0];   // 8 x 128 labW5b tile
    float* b5s = &Bs[0][0][0];   // 128 bias
    for (int i=tid; i<1024; i+=256){
        int t = i>>7, n = i&127;
        lw[i] = g_lw5b[(size_t)(l*NLS + t)*NH + n0 + n];
    }
    if (tid < 128) b5s[tid] = b5[n0 + tid];
    __syncthreads();

    #pragma unroll
    for (int i=0;i<8;i++){
        int mloc = ty*8 + i;
        int bs = bsbase + mloc;
        int m  = m0 + mloc;
        float a8[8];
        *(float4*)&a8[0] = *(const float4*)(g_a + (size_t)m*NLS);
        *(float4*)&a8[4] = *(const float4*)(g_a + (size_t)m*NLS + 4);
        int n = n0 + tx*8;
        const float* t1p = g_T1 + (size_t)bs*NH + n;
        float o[8];
        #pragma unroll
        for (int j=0;j<4;j++){ float2 p = up2(acc[i][j]); o[2*j]=p.x; o[2*j+1]=p.y; }
        #pragma unroll
        for (int j=0;j<8;j++){
            float v = o[j] + t1p[j] + b5s[tx*8 + j];
            #pragma unroll
            for (int t=0;t<8;t++) v += a8[t]*lw[t*128 + tx*8 + j];
            o[j] = tanhf(v);
        }
        float* op = out + ((size_t)bs*NL + l)*NH + n;
        *(float4*)op     = make_float4(o[0],o[1],o[2],o[3]);
        *(float4*)(op+4) = make_float4(o[4],o[5],o[6],o[7]);
    }
}

// ---------------- launch ----------------
extern "C" void kernel_launch(void* const* d_in, const int* in_sizes, int n_in,
                              void* d_out, int out_size)
{
    const float* token = (const float*)d_in[0];
    const float* lemb  = (const float*)d_in[1];
    const float* imask = (const float*)d_in[2];
    const float* lmask = (const float*)d_in[3];
    const float* W1    = (const float*)d_in[4];
    const float* W2    = (const float*)d_in[5];
    const float* W5    = (const float*)d_in[6];
    const float* b5    = (const float*)d_in[7];
    float* out = (float*)d_out;

    float *p_tkn, *p_T1;
    cudaGetSymbolAddress((void**)&p_tkn, g_tkn);
    cudaGetSymbolAddress((void**)&p_T1,  g_T1);

    klab <<<NL*NLS, 256>>>(lemb, W2);
    klw5b<<<NL*NLS, 256>>>(W5);
    // tkn = token @ W1^T   [2048,768]x[768,768]
    gemm_plain<<<dim3(6,16), 256>>>(token, NH, W1, NH, p_tkn, NH, NH);
    // T1 = tkn @ W5a^T
    gemm_plain<<<dim3(6,16), 256>>>(p_tkn, NH, W5, 3072, p_T1, NH, NH);
    k_scores<<<NBS, 256>>>(lmask, imask);
    k_q2c<<<NB*NL, 256>>>();
    k_xy<<<dim3(NBS/8, NL), 256>>>();
    gemm_final<<<dim3(6, MFIN/128), 256>>>(W5, b5, out);
}

// round 4
// speedup vs baseline: 1.4195x; 1.4195x over previous
#include <cuda_runtime.h>
#include <cstdint>
#include <math.h>

#define NB 8
#define NS 256
#define NH 768
#define NL 20
#define NLS 8
#define NE 300
#define NEGV -10000.0f
#define NBS (NB*NS)        /* 2048 */
#define MFIN (NBS*NL)      /* 40960 */
#define KFIN 1536
#define KITER 48           /* 1536/32 */

// ---------------- scratch (static device memory; no allocation) ----------------
__device__ float g_tkn[NBS*NH];
__device__ float g_T1 [NBS*NH];
__device__ float g_lab[NL*NLS*NH];
__device__ float g_lw5b[NL*NLS*NH];
__device__ float g_a  [MFIN*NLS];
__device__ float g_bin[NB*NL*NS];
__device__ float g_q2c[NB*NL*NH];
__device__ float g_XY [(size_t)MFIN*KFIN];   // tf32-rounded, [l*2048+bs][1536]
__device__ float g_W5r[NH*KFIN];             // tf32-rounded W5[:,1536:3072], [768][1536]

// ---------------- f32x2 helpers (SIMT GEMMs) ----------------
__device__ __forceinline__ unsigned long long pk2(float x){
    unsigned long long r; asm("mov.b64 %0, {%1, %1};" : "=l"(r) : "f"(x)); return r;
}
__device__ __forceinline__ unsigned long long fma2(unsigned long long a,
                                                   unsigned long long b,
                                                   unsigned long long c){
    unsigned long long d;
    asm("fma.rn.f32x2 %0, %1, %2, %3;" : "=l"(d) : "l"(a), "l"(b), "l"(c));
    return d;
}
__device__ __forceinline__ float2 up2(unsigned long long v){
    float2 f; asm("mov.b64 {%0, %1}, %2;" : "=f"(f.x), "=f"(f.y) : "l"(v)); return f;
}

// ---------------- misc helpers ----------------
__device__ __forceinline__ uint32_t smem_u32(const void* p){
    uint32_t a;
    asm("{ .reg .u64 t; cvta.to.shared.u64 t, %1; cvt.u32.u64 %0, t; }" : "=r"(a) : "l"(p));
    return a;
}
__device__ __forceinline__ float tf32r(float x){
    uint32_t u; asm("cvt.rna.tf32.f32 %0, %1;" : "=r"(u) : "f"(x));
    return __uint_as_float(u);
}
__device__ __forceinline__ void cpasync16(uint32_t dst, const void* src){
    asm volatile("cp.async.cg.shared.global [%0], [%1], 16;" :: "r"(dst), "l"(src));
}
#define CP_COMMIT() asm volatile("cp.async.commit_group;" ::: "memory")
#define CP_WAIT(n)  asm volatile("cp.async.wait_group " #n ";" ::: "memory")

// mma.sync tf32 m16n8k8 (baseline PTX, legacy HMMA pipe on sm_103)
#define MMA1688(c, a, b) \
    asm volatile("mma.sync.aligned.m16n8k8.row.col.f32.tf32.tf32.f32 " \
        "{%0,%1,%2,%3}, {%4,%5,%6,%7}, {%8,%9}, {%0,%1,%2,%3};" \
        : "+f"((c)[0]), "+f"((c)[1]), "+f"((c)[2]), "+f"((c)[3]) \
        : "r"((a)[0]), "r"((a)[1]), "r"((a)[2]), "r"((a)[3]), \
          "r"((b)[0]), "r"((b)[1]))

// swizzled smem index (floats): row*32 cols, 16B-group XOR by row&7
__device__ __forceinline__ int swidx(int r, int c){
    return r*32 + ((((c>>2) ^ (r&7))<<2) | (c&3));
}

// ---------------- lab = label_embs @ W2^T ----------------
__global__ void klab(const float* __restrict__ lemb, const float* __restrict__ W2){
    __shared__ float er[NE];
    int lt = blockIdx.x;
    for (int i = threadIdx.x; i < NE; i += blockDim.x) er[i] = lemb[lt*NE + i];
    __syncthreads();
    for (int o = threadIdx.x; o < NH; o += blockDim.x){
        const float* w = W2 + (size_t)o*NE;
        float s = 0.f;
        #pragma unroll 4
        for (int e = 0; e < NE; e++) s += er[e]*w[e];
        g_lab[lt*NH + o] = s;
    }
}

// ---------------- labW5b = lab @ W5b^T ----------------
__global__ void klw5b(const float* __restrict__ W5){
    __shared__ float lr[NH];
    int lt = blockIdx.x;
    for (int i = threadIdx.x; i < NH; i += blockDim.x) lr[i] = g_lab[lt*NH + i];
    __syncthreads();
    for (int o = threadIdx.x; o < NH; o += blockDim.x){
        const float4* w = (const float4*)(W5 + (size_t)o*3072 + NH);
        const float4* a = (const float4*)lr;
        float s = 0.f;
        #pragma unroll 4
        for (int i = 0; i < NH/4; i++){
            float4 x = a[i], y = w[i];
            s += x.x*y.x + x.y*y.y + x.z*y.z + x.w*y.w;
        }
        g_lw5b[lt*NH + o] = s;
    }
}

// ---------------- W5[c|d] -> tf32-rounded compact [768][1536] ----------------
__global__ void k_w5r(const float* __restrict__ W5){
    int idx = blockIdx.x*256 + threadIdx.x;
    if (idx >= NH*KFIN) return;
    int o = idx / KFIN, k = idx - o*KFIN;
    g_W5r[idx] = tf32r(W5[(size_t)o*3072 + 1536 + k]);
}

// ---------------- generic 128x128 fp32x2 GEMM: C[m,n] = sum_k A[m,k]*B[n,k] ----------------
__global__ __launch_bounds__(256,2) void gemm_plain(
    const float* __restrict__ A, int lda,
    const float* __restrict__ B, int ldb,
    float* __restrict__ C, int ldc, int Kdim)
{
    __shared__ float As[2][8][128];
    __shared__ float Bs[2][8][128];
    const int tid = threadIdx.x;
    const int m0 = blockIdx.y*128, n0 = blockIdx.x*128;
    const int lrow = tid>>1, lcol = (tid&1)*4;
    const float* Ag = A + (size_t)(m0+lrow)*lda + lcol;
    const float* Bg = B + (size_t)(n0+lrow)*ldb + lcol;
    const int tx = tid&15, ty = tid>>4;

    unsigned long long acc[8][4];
    #pragma unroll
    for (int i=0;i<8;i++)
        #pragma unroll
        for (int j=0;j<4;j++) acc[i][j]=0ull;

    const int nk = Kdim>>3;
    float4 ra = *(const float4*)Ag;
    float4 rb = *(const float4*)Bg;
    #pragma unroll
    for (int j=0;j<4;j++){
        As[0][lcol+j][lrow] = ((const float*)&ra)[j];
        Bs[0][lcol+j][lrow] = ((const float*)&rb)[j];
    }
    __syncthreads();
    int buf = 0;
    for (int kt=0; kt<nk; kt++){
        float4 na, nb;
        if (kt+1 < nk){
            na = *(const float4*)(Ag + (size_t)(kt+1)*8);
            nb = *(const float4*)(Bg + (size_t)(kt+1)*8);
        }
        #pragma unroll
        for (int k=0;k<8;k++){
            float av[8];
            *(float4*)&av[0] = *(const float4*)&As[buf][k][ty*8];
            *(float4*)&av[4] = *(const float4*)&As[buf][k][ty*8+4];
            unsigned long long b2[4];
            #pragma unroll
            for (int j=0;j<4;j++)
                b2[j] = *(const unsigned long long*)&Bs[buf][k][tx*8+2*j];
            #pragma unroll
            for (int i=0;i<8;i++){
                unsigned long long a2 = pk2(av[i]);
                #pragma unroll
                for (int j=0;j<4;j++) acc[i][j] = fma2(a2, b2[j], acc[i][j]);
            }
        }
        if (kt+1 < nk){
            buf ^= 1;
            #pragma unroll
            for (int j=0;j<4;j++){
                As[buf][lcol+j][lrow] = ((const float*)&na)[j];
                Bs[buf][lcol+j][lrow] = ((const float*)&nb)[j];
            }
        }
        __syncthreads();
    }
    #pragma unroll
    for (int i=0;i<8;i++){
        int m = m0 + ty*8 + i;
        float o[8];
        #pragma unroll
        for (int j=0;j<4;j++){ float2 p = up2(acc[i][j]); o[2*j]=p.x; o[2*j+1]=p.y; }
        float* cp = C + (size_t)m*ldc + n0 + tx*8;
        *(float4*)cp     = make_float4(o[0],o[1],o[2],o[3]);
        *(float4*)(cp+4) = make_float4(o[4],o[5],o[6],o[7]);
    }
}

// ---------------- scores + softmax over t + rowmax ----------------
__global__ void k_scores(const float* __restrict__ lmask, const float* __restrict__ imask){
    __shared__ float tr[NH];
    __shared__ float sc[NL*NLS];
    int bs = blockIdx.x;
    int b = bs >> 8;
    int tid = threadIdx.x;
    for (int i=tid; i<NH; i+=blockDim.x) tr[i] = g_tkn[(size_t)bs*NH + i];
    __syncthreads();
    if (tid < NL*NLS){
        const float4* lr = (const float4*)(g_lab + (size_t)tid*NH);
        const float4* tv = (const float4*)tr;
        float s = 0.f;
        #pragma unroll 4
        for (int i=0;i<NH/4;i++){
            float4 x = lr[i], y = tv[i];
            s += x.x*y.x + x.y*y.y + x.z*y.z + x.w*y.w;
        }
        sc[tid] = s + (1.0f - lmask[tid])*NEGV;
    }
    __syncthreads();
    if (tid < NL){
        int l = tid;
        float mx = -1e30f;
        #pragma unroll
        for (int t=0;t<NLS;t++) mx = fmaxf(mx, sc[l*NLS+t]);
        float ex[NLS]; float sm = 0.f;
        #pragma unroll
        for (int t=0;t<NLS;t++){ ex[t] = expf(sc[l*NLS+t]-mx); sm += ex[t]; }
        float inv = 1.0f/sm;
        int m = l*NBS + bs;
        #pragma unroll
        for (int t=0;t<NLS;t++) g_a[(size_t)m*NLS + t] = ex[t]*inv;
        g_bin[(b*NL + l)*NS + (bs & 255)] = mx + (1.0f - imask[bs])*NEGV;
    }
}

// ---------------- softmax over s + q2c ----------------
__global__ void k_q2c(){
    __shared__ float w[NS];
    __shared__ float red[256];
    int blk = blockIdx.x;
    int b = blk / NL;
    int tid = threadIdx.x;
    float v = g_bin[blk*NS + tid];
    red[tid] = v; __syncthreads();
    for (int off=128; off>0; off>>=1){
        if (tid < off) red[tid] = fmaxf(red[tid], red[tid+off]);
        __syncthreads();
    }
    float mx = red[0]; __syncthreads();
    float e = expf(v - mx);
    red[tid] = e; __syncthreads();
    for (int off=128; off>0; off>>=1){
        if (tid < off) red[tid] += red[tid+off];
        __syncthreads();
    }
    float inv = 1.0f/red[0];
    w[tid] = e*inv;
    __syncthreads();
    for (int h=tid; h<NH; h+=blockDim.x){
        float acc = 0.f;
        #pragma unroll 4
        for (int s=0;s<NS;s++) acc += w[s]*g_tkn[(size_t)(b*NS+s)*NH + h];
        g_q2c[(size_t)blk*NH + h] = acc;
    }
}

// ------- build XY = [tkn*c2q | tkn*q2c] (tf32-rounded), m = l*2048+bs -------
__global__ void k_xy(){
    __shared__ float labs[NLS*NH];
    int l = blockIdx.y;
    int bs0 = blockIdx.x*8;
    int tid = threadIdx.x;
    for (int i=tid; i<NLS*NH; i+=blockDim.x) labs[i] = g_lab[(size_t)l*NLS*NH + i];
    __syncthreads();
    for (int j=0;j<8;j++){
        int bs = bs0 + j;
        int b = bs >> 8;
        int m = l*NBS + bs;
        const float* ap = g_a + (size_t)m*NLS;
        float a0=ap[0],a1=ap[1],a2=ap[2],a3=ap[3],a4=ap[4],a5=ap[5],a6=ap[6],a7=ap[7];
        const float* q = g_q2c + (size_t)(b*NL + l)*NH;
        const float* tk = g_tkn + (size_t)bs*NH;
        float* xy = g_XY + (size_t)m*KFIN;
        for (int k=tid; k<NH; k+=blockDim.x){
            float c2 = a0*labs[k]        + a1*labs[NH+k]   + a2*labs[2*NH+k] + a3*labs[3*NH+k]
                     + a4*labs[4*NH+k]   + a5*labs[5*NH+k] + a6*labs[6*NH+k] + a7*labs[7*NH+k];
            float t = tk[k];
            xy[k]      = tf32r(t*c2);
            xy[NH + k] = tf32r(t*q[k]);
        }
    }
}

// ---------------- tf32 mma.sync GEMM 128x128x32 + fused epilogue ----------------
// dynamic smem: A stages 3 x 16KB at [0,49152), B stages 3 x 16KB at [49152, 98304)
#define MMA_STAGES 3
#define SMEM_MMA (MMA_STAGES*2*16384)

__global__ __launch_bounds__(256,2) void gemm_mma(const float* __restrict__ b5,
                                                  float* __restrict__ outp)
{
    extern __shared__ char smp[];
    const int tid = threadIdx.x;
    const int wid = tid>>5, lane = tid&31;
    const int g = lane>>2, tg = lane&3;
    const int wr = wid>>2, wc = wid&3;          // warp tile: 64 (m) x 32 (n)
    const int nt = blockIdx.x, mt = blockIdx.y;
    const int n0 = nt*128, m0 = mt*128;
    const int l = m0 >> 11;
    const int bsbase = m0 & 2047;

    const uint32_t sbase = smem_u32(smp);
    const char* Agb = (const char*)g_XY  + ((size_t)m0*KFIN)*4;
    const char* Bgb = (const char*)g_W5r + ((size_t)n0*KFIN)*4;

    // per-thread cp.async assignment: row = tid>>1 (0..127), 4 x 16B groups
    const int crow = tid>>1;
    const int cgb = (tid&1)*4;
    const int r7x = crow&7;
    const size_t grow = (size_t)crow*(KFIN*4);

    float acc[4][4][4];
    #pragma unroll
    for (int i=0;i<4;i++)
        #pragma unroll
        for (int j=0;j<4;j++)
            #pragma unroll
            for (int c=0;c<4;c++) acc[i][j][c] = 0.f;

    // prologue: stages 0,1
    #pragma unroll
    for (int s=0;s<2;s++){
        uint32_t sA = sbase + s*16384;
        uint32_t sB = sbase + 49152 + s*16384;
        const char* Ab = Agb + (size_t)s*128;   // kt*32 floats = 128B
        const char* Bb = Bgb + (size_t)s*128;
        #pragma unroll
        for (int q=0;q<4;q++){
            int cg = cgb+q;
            cpasync16(sA + crow*128 + ((cg^r7x)<<4), Ab + grow + cg*16);
        }
        #pragma unroll
        for (int q=0;q<4;q++){
            int cg = cgb+q;
            cpasync16(sB + crow*128 + ((cg^r7x)<<4), Bb + grow + cg*16);
        }
        CP_COMMIT();
    }

    int s_cur = 0, s_nxt = 2;
    for (int kt=0; kt<KITER; kt++){
        CP_WAIT(1);
        __syncthreads();
        if (kt+2 < KITER){
            uint32_t sA = sbase + s_nxt*16384;
            uint32_t sB = sbase + 49152 + s_nxt*16384;
            const char* Ab = Agb + (size_t)(kt+2)*128;
            const char* Bb = Bgb + (size_t)(kt+2)*128;
            #pragma unroll
            for (int q=0;q<4;q++){
                int cg = cgb+q;
                cpasync16(sA + crow*128 + ((cg^r7x)<<4), Ab + grow + cg*16);
            }
            #pragma unroll
            for (int q=0;q<4;q++){
                int cg = cgb+q;
                cpasync16(sB + crow*128 + ((cg^r7x)<<4), Bb + grow + cg*16);
            }
        }
        CP_COMMIT();

        const uint32_t* As32 = (const uint32_t*)(smp + s_cur*16384);
        const uint32_t* Bs32 = (const uint32_t*)(smp + 49152 + s_cur*16384);
        #pragma unroll
        for (int ks=0; ks<4; ks++){
            const int kc = ks*8 + tg;
            uint32_t af[4][4], bf[4][2];
            #pragma unroll
            for (int i=0;i<4;i++){
                int r0 = wr*64 + i*16 + g;
                af[i][0] = As32[swidx(r0,   kc)];
                af[i][1] = As32[swidx(r0+8, kc)];
                af[i][2] = As32[swidx(r0,   kc+4)];
                af[i][3] = As32[swidx(r0+8, kc+4)];
            }
            #pragma unroll
            for (int j=0;j<4;j++){
                int rb = wc*32 + j*8 + g;
                bf[j][0] = Bs32[swidx(rb, kc)];
                bf[j][1] = Bs32[swidx(rb, kc+4)];
            }
            #pragma unroll
            for (int i=0;i<4;i++)
                #pragma unroll
                for (int j=0;j<4;j++)
                    MMA1688(acc[i][j], af[i], bf[j]);
        }
        s_cur++; if (s_cur==MMA_STAGES) s_cur=0;
        s_nxt++; if (s_nxt==MMA_STAGES) s_nxt=0;
    }

    // ---- fused epilogue: + T1 + a@lw5b + b5, tanh ----
    CP_WAIT(0);
    __syncthreads();
    float* lw  = (float*)smp;            // 8 x 128
    float* b5s = (float*)(smp + 4096);   // 128
    for (int i=tid; i<8*128; i+=256)
        lw[i] = g_lw5b[(size_t)(l*NLS + (i>>7))*NH + n0 + (i&127)];
    if (tid < 128) b5s[tid] = b5[n0 + tid];
    __syncthreads();

    #pragma unroll
    for (int i=0;i<4;i++){
        #pragma unroll
        for (int h=0;h<2;h++){
            int mloc = wr*64 + i*16 + g + h*8;
            int m = m0 + mloc;
            int bs = bsbase + mloc;
            float a8[8];
            *(float4*)&a8[0] = *(const float4*)(g_a + (size_t)m*NLS);
            *(float4*)&a8[4] = *(const float4*)(g_a + (size_t)m*NLS + 4);
            const float* t1r = g_T1 + (size_t)bs*NH + n0;
            float* orow = outp + ((size_t)bs*NL + l)*NH + n0;
            #pragma unroll
            for (int j=0;j<4;j++){
                int nl = wc*32 + j*8 + 2*tg;
                float2 t1v = *(const float2*)(t1r + nl);
                float v0 = acc[i][j][h*2]   + t1v.x + b5s[nl];
                float v1 = acc[i][j][h*2+1] + t1v.y + b5s[nl+1];
                #pragma unroll
                for (int t=0;t<8;t++){
                    v0 += a8[t]*lw[t*128 + nl];
                    v1 += a8[t]*lw[t*128 + nl + 1];
                }
                float2 o2 = make_float2(tanhf(v0), tanhf(v1));
                *(float2*)(orow + nl) = o2;
            }
        }
    }
}

// ---------------- launch ----------------
extern "C" void kernel_launch(void* const* d_in, const int* in_sizes, int n_in,
                              void* d_out, int out_size)
{
    const float* token = (const float*)d_in[0];
    const float* lemb  = (const float*)d_in[1];
    const float* imask = (const float*)d_in[2];
    const float* lmask = (const float*)d_in[3];
    const float* W1    = (const float*)d_in[4];
    const float* W2    = (const float*)d_in[5];
    const float* W5    = (const float*)d_in[6];
    const float* b5    = (const float*)d_in[7];
    float* out = (float*)d_out;

    float *p_tkn, *p_T1;
    cudaGetSymbolAddress((void**)&p_tkn, g_tkn);
    cudaGetSymbolAddress((void**)&p_T1,  g_T1);

    static int smem_set = 0;
    if (!smem_set){
        cudaFuncSetAttribute(gemm_mma, cudaFuncAttributeMaxDynamicSharedMemorySize, SMEM_MMA);
        smem_set = 1;
    }

    klab <<<NL*NLS, 256>>>(lemb, W2);
    klw5b<<<NL*NLS, 256>>>(W5);
    k_w5r<<<(NH*KFIN + 255)/256, 256>>>(W5);
    gemm_plain<<<dim3(6,16), 256>>>(token, NH, W1, NH, p_tkn, NH, NH);
    gemm_plain<<<dim3(6,16), 256>>>(p_tkn, NH, W5, 3072, p_T1, NH, NH);
    k_scores<<<NBS, 256>>>(lmask, imask);
    k_q2c<<<NB*NL, 256>>>();
    k_xy<<<dim3(NBS/8, NL), 256>>>();
    gemm_mma<<<dim3(6, MFIN/128), 256, SMEM_MMA>>>(b5, out);
}

// round 5
// speedup vs baseline: 2.5281x; 1.7809x over previous
#include <cuda_runtime.h>
#include <cuda_fp16.h>
#include <cstdint>
#include <math.h>

#define NB 8
#define NS 256
#define NH 768
#define NL 20
#define NLS 8
#define NE 300
#define NEGV -10000.0f
#define NBS (NB*NS)        /* 2048 */
#define MFIN (NBS*NL)      /* 40960 */
#define KFIN 1536
#define KITER 48           /* 1536/32 */

// ---------------- scratch (static device memory; no allocation) ----------------
__device__ float g_tkn[NBS*NH];
__device__ float g_T1 [NBS*NH];
__device__ float g_lab[NL*NLS*NH];
__device__ float g_lw5b[NL*NLS*NH];
__device__ float g_a  [MFIN*NLS];
__device__ float g_bin[NB*NL*NS];
__device__ float g_q2c[NB*NL*NH];
__device__ __align__(128) __half g_XYh[(size_t)MFIN*KFIN];  // 126 MB fp16
__device__ __align__(128) __half g_W5h[NH*KFIN];            // fp16 W5[:,1536:3072]

// ---------------- f32x2 helpers (SIMT GEMMs) ----------------
__device__ __forceinline__ unsigned long long pk2(float x){
    unsigned long long r; asm("mov.b64 %0, {%1, %1};" : "=l"(r) : "f"(x)); return r;
}
__device__ __forceinline__ unsigned long long fma2(unsigned long long a,
                                                   unsigned long long b,
                                                   unsigned long long c){
    unsigned long long d;
    asm("fma.rn.f32x2 %0, %1, %2, %3;" : "=l"(d) : "l"(a), "l"(b), "l"(c));
    return d;
}
__device__ __forceinline__ float2 up2(unsigned long long v){
    float2 f; asm("mov.b64 {%0, %1}, %2;" : "=f"(f.x), "=f"(f.y) : "l"(v)); return f;
}

// ---------------- misc helpers ----------------
__device__ __forceinline__ uint32_t smem_u32(const void* p){
    uint32_t a;
    asm("{ .reg .u64 t; cvta.to.shared.u64 t, %1; cvt.u32.u64 %0, t; }" : "=r"(a) : "l"(p));
    return a;
}
__device__ __forceinline__ void cpasync16(uint32_t dst, const void* src){
    asm volatile("cp.async.cg.shared.global [%0], [%1], 16;" :: "r"(dst), "l"(src));
}
#define CP_COMMIT() asm volatile("cp.async.commit_group;" ::: "memory")
#define CP_WAIT(n)  asm volatile("cp.async.wait_group " #n ";" ::: "memory")

#define LDSM4(r0,r1,r2,r3, addr) \
    asm volatile("ldmatrix.sync.aligned.m8n8.x4.shared.b16 {%0,%1,%2,%3}, [%4];" \
        : "=r"(r0), "=r"(r1), "=r"(r2), "=r"(r3) : "r"(addr))

#define MMAH(c, a0,a1,a2,a3, b0,b1) \
    asm volatile("mma.sync.aligned.m16n8k16.row.col.f32.f16.f16.f32 " \
        "{%0,%1,%2,%3}, {%4,%5,%6,%7}, {%8,%9}, {%0,%1,%2,%3};" \
        : "+f"((c)[0]), "+f"((c)[1]), "+f"((c)[2]), "+f"((c)[3]) \
        : "r"(a0), "r"(a1), "r"(a2), "r"(a3), "r"(b0), "r"(b1))

// crosswise swizzle: logical (row, 16B-chunk cg in 0..3) of a [rows x 64B] tile
// physical: p = row>>1, c = ((row&1)*4 + cg) ^ (p&7), byte = p*128 + c*16
__device__ __forceinline__ uint32_t swzh(int row, int cg){
    int p = row >> 1;
    int c = (((row & 1) << 2) | cg) ^ (p & 7);
    return (uint32_t)(p*128 + c*16);
}

// ---------------- lab = label_embs @ W2^T ----------------
__global__ void klab(const float* __restrict__ lemb, const float* __restrict__ W2){
    __shared__ float er[NE];
    int lt = blockIdx.x;
    for (int i = threadIdx.x; i < NE; i += blockDim.x) er[i] = lemb[lt*NE + i];
    __syncthreads();
    for (int o = threadIdx.x; o < NH; o += blockDim.x){
        const float* w = W2 + (size_t)o*NE;
        float s = 0.f;
        #pragma unroll 4
        for (int e = 0; e < NE; e++) s += er[e]*w[e];
        g_lab[lt*NH + o] = s;
    }
}

// ---------------- labW5b = lab @ W5b^T ----------------
__global__ void klw5b(const float* __restrict__ W5){
    __shared__ float lr[NH];
    int lt = blockIdx.x;
    for (int i = threadIdx.x; i < NH; i += blockDim.x) lr[i] = g_lab[lt*NH + i];
    __syncthreads();
    for (int o = threadIdx.x; o < NH; o += blockDim.x){
        const float4* w = (const float4*)(W5 + (size_t)o*3072 + NH);
        const float4* a = (const float4*)lr;
        float s = 0.f;
        #pragma unroll 4
        for (int i = 0; i < NH/4; i++){
            float4 x = a[i], y = w[i];
            s += x.x*y.x + x.y*y.y + x.z*y.z + x.w*y.w;
        }
        g_lw5b[lt*NH + o] = s;
    }
}

// ---------------- W5[c|d] -> fp16 compact [768][1536] ----------------
__global__ void k_w5h(const float* __restrict__ W5){
    int idx = blockIdx.x*256 + threadIdx.x;
    if (idx >= NH*KFIN) return;
    int o = idx / KFIN, k = idx - o*KFIN;
    g_W5h[idx] = __float2half(W5[(size_t)o*3072 + 1536 + k]);
}

// ---------------- generic 128x128 fp32x2 GEMM: C[m,n] = sum_k A[m,k]*B[n,k] ----------------
__global__ __launch_bounds__(256,2) void gemm_plain(
    const float* __restrict__ A, int lda,
    const float* __restrict__ B, int ldb,
    float* __restrict__ C, int ldc, int Kdim)
{
    __shared__ float As[2][8][128];
    __shared__ float Bs[2][8][128];
    const int tid = threadIdx.x;
    const int m0 = blockIdx.y*128, n0 = blockIdx.x*128;
    const int lrow = tid>>1, lcol = (tid&1)*4;
    const float* Ag = A + (size_t)(m0+lrow)*lda + lcol;
    const float* Bg = B + (size_t)(n0+lrow)*ldb + lcol;
    const int tx = tid&15, ty = tid>>4;

    unsigned long long acc[8][4];
    #pragma unroll
    for (int i=0;i<8;i++)
        #pragma unroll
        for (int j=0;j<4;j++) acc[i][j]=0ull;

    const int nk = Kdim>>3;
    float4 ra = *(const float4*)Ag;
    float4 rb = *(const float4*)Bg;
    #pragma unroll
    for (int j=0;j<4;j++){
        As[0][lcol+j][lrow] = ((const float*)&ra)[j];
        Bs[0][lcol+j][lrow] = ((const float*)&rb)[j];
    }
    __syncthreads();
    int buf = 0;
    for (int kt=0; kt<nk; kt++){
        float4 na, nb;
        if (kt+1 < nk){
            na = *(const float4*)(Ag + (size_t)(kt+1)*8);
            nb = *(const float4*)(Bg + (size_t)(kt+1)*8);
        }
        #pragma unroll
        for (int k=0;k<8;k++){
            float av[8];
            *(float4*)&av[0] = *(const float4*)&As[buf][k][ty*8];
            *(float4*)&av[4] = *(const float4*)&As[buf][k][ty*8+4];
            unsigned long long b2[4];
            #pragma unroll
            for (int j=0;j<4;j++)
                b2[j] = *(const unsigned long long*)&Bs[buf][k][tx*8+2*j];
            #pragma unroll
            for (int i=0;i<8;i++){
                unsigned long long a2 = pk2(av[i]);
                #pragma unroll
                for (int j=0;j<4;j++) acc[i][j] = fma2(a2, b2[j], acc[i][j]);
            }
        }
        if (kt+1 < nk){
            buf ^= 1;
            #pragma unroll
            for (int j=0;j<4;j++){
                As[buf][lcol+j][lrow] = ((const float*)&na)[j];
                Bs[buf][lcol+j][lrow] = ((const float*)&nb)[j];
            }
        }
        __syncthreads();
    }
    #pragma unroll
    for (int i=0;i<8;i++){
        int m = m0 + ty*8 + i;
        float o[8];
        #pragma unroll
        for (int j=0;j<4;j++){ float2 p = up2(acc[i][j]); o[2*j]=p.x; o[2*j+1]=p.y; }
        float* cp = C + (size_t)m*ldc + n0 + tx*8;
        *(float4*)cp     = make_float4(o[0],o[1],o[2],o[3]);
        *(float4*)(cp+4) = make_float4(o[4],o[5],o[6],o[7]);
    }
}

// ---------------- scores + softmax over t + rowmax ----------------
__global__ void k_scores(const float* __restrict__ lmask, const float* __restrict__ imask){
    __shared__ float tr[NH];
    __shared__ float sc[NL*NLS];
    int bs = blockIdx.x;
    int b = bs >> 8;
    int tid = threadIdx.x;
    for (int i=tid; i<NH; i+=blockDim.x) tr[i] = g_tkn[(size_t)bs*NH + i];
    __syncthreads();
    if (tid < NL*NLS){
        const float4* lr = (const float4*)(g_lab + (size_t)tid*NH);
        const float4* tv = (const float4*)tr;
        float s = 0.f;
        #pragma unroll 4
        for (int i=0;i<NH/4;i++){
            float4 x = lr[i], y = tv[i];
            s += x.x*y.x + x.y*y.y + x.z*y.z + x.w*y.w;
        }
        sc[tid] = s + (1.0f - lmask[tid])*NEGV;
    }
    __syncthreads();
    if (tid < NL){
        int l = tid;
        float mx = -1e30f;
        #pragma unroll
        for (int t=0;t<NLS;t++) mx = fmaxf(mx, sc[l*NLS+t]);
        float ex[NLS]; float sm = 0.f;
        #pragma unroll
        for (int t=0;t<NLS;t++){ ex[t] = expf(sc[l*NLS+t]-mx); sm += ex[t]; }
        float inv = 1.0f/sm;
        int m = l*NBS + bs;
        #pragma unroll
        for (int t=0;t<NLS;t++) g_a[(size_t)m*NLS + t] = ex[t]*inv;
        g_bin[(b*NL + l)*NS + (bs & 255)] = mx + (1.0f - imask[bs])*NEGV;
    }
}

// ---------------- softmax over s + q2c ----------------
__global__ void k_q2c(){
    __shared__ float w[NS];
    __shared__ float red[256];
    int blk = blockIdx.x;
    int b = blk / NL;
    int tid = threadIdx.x;
    float v = g_bin[blk*NS + tid];
    red[tid] = v; __syncthreads();
    for (int off=128; off>0; off>>=1){
        if (tid < off) red[tid] = fmaxf(red[tid], red[tid+off]);
        __syncthreads();
    }
    float mx = red[0]; __syncthreads();
    float e = expf(v - mx);
    red[tid] = e; __syncthreads();
    for (int off=128; off>0; off>>=1){
        if (tid < off) red[tid] += red[tid+off];
        __syncthreads();
    }
    float inv = 1.0f/red[0];
    w[tid] = e*inv;
    __syncthreads();
    for (int h=tid; h<NH; h+=blockDim.x){
        float acc = 0.f;
        #pragma unroll 4
        for (int s=0;s<NS;s++) acc += w[s]*g_tkn[(size_t)(b*NS+s)*NH + h];
        g_q2c[(size_t)blk*NH + h] = acc;
    }
}

// ------- build XY = [tkn*c2q | tkn*q2c] (fp16), m = l*2048+bs -------
__global__ void k_xy(){
    __shared__ float labs[NLS*NH];
    int l = blockIdx.y;
    int bs0 = blockIdx.x*8;
    int tid = threadIdx.x;
    for (int i=tid; i<NLS*NH; i+=blockDim.x) labs[i] = g_lab[(size_t)l*NLS*NH + i];
    __syncthreads();
    for (int j=0;j<8;j++){
        int bs = bs0 + j;
        int b = bs >> 8;
        int m = l*NBS + bs;
        const float* ap = g_a + (size_t)m*NLS;
        float a0=ap[0],a1=ap[1],a2=ap[2],a3=ap[3],a4=ap[4],a5=ap[5],a6=ap[6],a7=ap[7];
        const float* q = g_q2c + (size_t)(b*NL + l)*NH;
        const float* tk = g_tkn + (size_t)bs*NH;
        __half* xy = g_XYh + (size_t)m*KFIN;
        for (int k=tid; k<NH; k+=blockDim.x){
            float c2 = a0*labs[k]        + a1*labs[NH+k]   + a2*labs[2*NH+k] + a3*labs[3*NH+k]
                     + a4*labs[4*NH+k]   + a5*labs[5*NH+k] + a6*labs[6*NH+k] + a7*labs[7*NH+k];
            float t = tk[k];
            xy[k]      = __float2half(t*c2);
            xy[NH + k] = __float2half(t*q[k]);
        }
    }
}

// ---------------- fp16 mma.sync GEMM 128x128x32 + fused epilogue ----------------
// dynamic smem: A stages 4 x 8KB at [0,32768), B stages 4 x 8KB at [32768,65536)
#define HSTAGES 4
#define SMEM_H (HSTAGES*2*8192)

__global__ __launch_bounds__(256,2) void gemm_h(const float* __restrict__ b5,
                                                float* __restrict__ outp)
{
    extern __shared__ char smp[];
    const int tid = threadIdx.x;
    const int wid = tid>>5, lane = tid&31;
    const int g = lane>>2, tg = lane&3;
    const int wr = wid>>2, wc = wid&3;          // warp tile: 64 (m) x 32 (n)
    const int nt = blockIdx.x, mt = blockIdx.y;
    const int n0 = nt*128, m0 = mt*128;
    const int l = m0 >> 11;
    const int bsbase = m0 & 2047;

    const uint32_t sbase = smem_u32(smp);
    const uint32_t stA = sbase;
    const uint32_t stB = sbase + HSTAGES*8192;
    const char* Agb = (const char*)g_XYh + (size_t)m0*KFIN*2;   // rows of 3072B
    const char* Bgb = (const char*)g_W5h + (size_t)n0*KFIN*2;

    // cp.async assignment: thread t -> rows (t>>2, t>>2 + 64), chunk cg = t&3
    const int crow = tid>>2;
    const int ccg  = tid&3;
    const uint32_t dA0 = swzh(crow,    ccg), dA1 = swzh(crow+64, ccg);
    const size_t gr0 = (size_t)crow*3072 + ccg*16;
    const size_t gr1 = (size_t)(crow+64)*3072 + ccg*16;

    // ldmatrix per-thread smem offsets
    uint32_t offA[4][2];
    #pragma unroll
    for (int i=0;i<4;i++)
        #pragma unroll
        for (int ks=0;ks<2;ks++){
            int row = wr*64 + i*16 + (lane&15);
            int cg = ks*2 + (lane>>4);
            offA[i][ks] = swzh(row, cg);
        }
    uint32_t offB[4];
    #pragma unroll
    for (int j=0;j<4;j++){
        int row = wc*32 + j*8 + (lane&7);
        int cg = lane>>3;
        offB[j] = swzh(row, cg);
    }

    float acc[4][4][4];
    #pragma unroll
    for (int i=0;i<4;i++)
        #pragma unroll
        for (int j=0;j<4;j++)
            #pragma unroll
            for (int c=0;c<4;c++) acc[i][j][c] = 0.f;

    // prologue: stages 0..2
    #pragma unroll
    for (int s=0;s<HSTAGES-1;s++){
        const char* Ab = Agb + (size_t)s*64;   // kt*32 halves = 64B
        const char* Bb = Bgb + (size_t)s*64;
        cpasync16(stA + s*8192 + dA0, Ab + gr0);
        cpasync16(stA + s*8192 + dA1, Ab + gr1);
        cpasync16(stB + s*8192 + dA0, Bb + gr0);
        cpasync16(stB + s*8192 + dA1, Bb + gr1);
        CP_COMMIT();
    }

    int s_cur = 0, s_nxt = HSTAGES-1;
    for (int kt=0; kt<KITER; kt++){
        CP_WAIT(2);
        __syncthreads();
        if (kt+HSTAGES-1 < KITER){
            const char* Ab = Agb + (size_t)(kt+HSTAGES-1)*64;
            const char* Bb = Bgb + (size_t)(kt+HSTAGES-1)*64;
            cpasync16(stA + s_nxt*8192 + dA0, Ab + gr0);
            cpasync16(stA + s_nxt*8192 + dA1, Ab + gr1);
            cpasync16(stB + s_nxt*8192 + dA0, Bb + gr0);
            cpasync16(stB + s_nxt*8192 + dA1, Bb + gr1);
        }
        CP_COMMIT();

        const uint32_t aB = stA + s_cur*8192;
        const uint32_t bB = stB + s_cur*8192;
        uint32_t bf[4][4];
        #pragma unroll
        for (int j=0;j<4;j++)
            LDSM4(bf[j][0], bf[j][1], bf[j][2], bf[j][3], bB + offB[j]);
        #pragma unroll
        for (int ks=0; ks<2; ks++){
            #pragma unroll
            for (int i=0;i<4;i++){
                uint32_t a0,a1,a2,a3;
                LDSM4(a0,a1,a2,a3, aB + offA[i][ks]);
                #pragma unroll
                for (int j=0;j<4;j++)
                    MMAH(acc[i][j], a0,a1,a2,a3, bf[j][ks*2], bf[j][ks*2+1]);
            }
        }
        s_cur++; if (s_cur==HSTAGES) s_cur=0;
        s_nxt++; if (s_nxt==HSTAGES) s_nxt=0;
    }

    // ---- fused epilogue: + T1 + a@lw5b + b5, tanh ----
    CP_WAIT(0);
    __syncthreads();
    float* lw  = (float*)smp;            // 8 x 128
    float* b5s = (float*)(smp + 4096);   // 128
    for (int i=tid; i<8*128; i+=256)
        lw[i] = g_lw5b[(size_t)(l*NLS + (i>>7))*NH + n0 + (i&127)];
    if (tid < 128) b5s[tid] = b5[n0 + tid];
    __syncthreads();

    #pragma unroll
    for (int i=0;i<4;i++){
        #pragma unroll
        for (int h=0;h<2;h++){
            int mloc = wr*64 + i*16 + g + h*8;
            int m = m0 + mloc;
            int bs = bsbase + mloc;
            float a8[8];
            *(float4*)&a8[0] = *(const float4*)(g_a + (size_t)m*NLS);
            *(float4*)&a8[4] = *(const float4*)(g_a + (size_t)m*NLS + 4);
            const float* t1r = g_T1 + (size_t)bs*NH + n0;
            float* orow = outp + ((size_t)bs*NL + l)*NH + n0;
            #pragma unroll
            for (int j=0;j<4;j++){
                int nl = wc*32 + j*8 + 2*tg;
                float2 t1v = *(const float2*)(t1r + nl);
                float v0 = acc[i][j][h*2]   + t1v.x + b5s[nl];
                float v1 = acc[i][j][h*2+1] + t1v.y + b5s[nl+1];
                #pragma unroll
                for (int t=0;t<8;t++){
                    v0 += a8[t]*lw[t*128 + nl];
                    v1 += a8[t]*lw[t*128 + nl + 1];
                }
                float2 o2 = make_float2(tanhf(v0), tanhf(v1));
                *(float2*)(orow + nl) = o2;
            }
        }
    }
}

// ---------------- launch ----------------
extern "C" void kernel_launch(void* const* d_in, const int* in_sizes, int n_in,
                              void* d_out, int out_size)
{
    const float* token = (const float*)d_in[0];
    const float* lemb  = (const float*)d_in[1];
    const float* imask = (const float*)d_in[2];
    const float* lmask = (const float*)d_in[3];
    const float* W1    = (const float*)d_in[4];
    const float* W2    = (const float*)d_in[5];
    const float* W5    = (const float*)d_in[6];
    const float* b5    = (const float*)d_in[7];
    float* out = (float*)d_out;

    float *p_tkn, *p_T1;
    cudaGetSymbolAddress((void**)&p_tkn, g_tkn);
    cudaGetSymbolAddress((void**)&p_T1,  g_T1);

    static int smem_set = 0;
    if (!smem_set){
        cudaFuncSetAttribute(gemm_h, cudaFuncAttributeMaxDynamicSharedMemorySize, SMEM_H);
        smem_set = 1;
    }

    klab <<<NL*NLS, 256>>>(lemb, W2);
    klw5b<<<NL*NLS, 256>>>(W5);
    k_w5h<<<(NH*KFIN + 255)/256, 256>>>(W5);
    gemm_plain<<<dim3(6,16), 256>>>(token, NH, W1, NH, p_tkn, NH, NH);
    gemm_plain<<<dim3(6,16), 256>>>(p_tkn, NH, W5, 3072, p_T1, NH, NH);
    k_scores<<<NBS, 256>>>(lmask, imask);
    k_q2c<<<NB*NL, 256>>>();
    k_xy<<<dim3(NBS/8, NL), 256>>>();
    gemm_h<<<dim3(6, MFIN/128), 256, SMEM_H>>>(b5, out);
}